// round 3
// baseline (speedup 1.0000x reference)
#include <cuda_runtime.h>
#include <cstdint>

#define NTOK   8192              // B*S
#define T_SLOT 16
#define E_DIM  1024              // token embedding floats (4096 B)
#define D_DIM  100               // entity embedding floats (400 B)
#define OUT_W  (E_DIM + D_DIM)   // 1124 floats (4496 B, 16B multiple)
#define WPB    8                 // warps per block

__global__ __launch_bounds__(32 * WPB)
void fuse_triples_tma_kernel(const int*   __restrict__ inputs,   // [NTOK]
                             const int*   __restrict__ triples,  // [NTOK,T,3]
                             const int*   __restrict__ flags,    // [NTOK,T]
                             const float* __restrict__ emb,      // [VOCAB,1024]
                             const float* __restrict__ ent,      // [ENT_VOCAB,100]
                             float*       __restrict__ out)      // [NTOK,1124]
{
    __shared__ alignas(128) float              buf[WPB][E_DIM];   // 4 KB / warp
    __shared__ alignas(8)   unsigned long long mbar[WPB];

    const int w     = threadIdx.x >> 5;
    const int lane  = threadIdx.x & 31;
    const int token = blockIdx.x * WPB + w;

    const uint32_t buf_addr  = (uint32_t)__cvta_generic_to_shared(&buf[w][0]);
    const uint32_t mbar_addr = (uint32_t)__cvta_generic_to_shared(&mbar[w]);

    const int vrow = inputs[token];                 // broadcast 4B load

    // ---- kick off bulk copy of the 4KB token-embedding row (TMA path) ----
    if (lane == 0) {
        asm volatile("mbarrier.init.shared::cta.b64 [%0], 1;"
                     :: "r"(mbar_addr) : "memory");
    }
    __syncwarp();
    if (lane == 0) {
        asm volatile("mbarrier.arrive.expect_tx.shared::cta.b64 _, [%0], %1;"
                     :: "r"(mbar_addr), "r"(4096u) : "memory");
        asm volatile("cp.async.bulk.shared::cta.global.mbarrier::complete_tx::bytes"
                     " [%0], [%1], %2, [%3];"
                     :: "r"(buf_addr),
                        "l"(emb + (size_t)vrow * E_DIM),
                        "r"(4096u), "r"(mbar_addr) : "memory");
    }

    // ---- decode triple slots, one per lane (lanes 0..15) — LDG path ----
    int e = -1;
    if (lane < T_SLOT) {
        const int f = flags[token * T_SLOT + lane];
        if (f == 1)      e = triples[(token * T_SLOT + lane) * 3 + 1]; // tail
        else if (f == 2) e = triples[(token * T_SLOT + lane) * 3 + 0]; // head
    }
    const unsigned vmask = __ballot_sync(0xffffffffu, e >= 0);
    const int cnt = __popc(vmask & 0xFFFFu);

    // ---- entity gather + average: lanes 0..24 own one float4 group ----
    float4 acc = make_float4(0.f, 0.f, 0.f, 0.f);
    #pragma unroll
    for (int j = 0; j < T_SLOT; ++j) {
        const int ej = __shfl_sync(0xffffffffu, e, j);
        if (ej >= 0 && lane < 25) {
            const float4 r = reinterpret_cast<const float4*>(
                                 ent + (size_t)ej * D_DIM)[lane];
            acc.x += r.x; acc.y += r.y; acc.z += r.z; acc.w += r.w;
        }
    }
    if (lane < 25) {
        const float inv = 1.0f / (float)(cnt > 0 ? cnt : 1);
        acc.x *= inv; acc.y *= inv; acc.z *= inv; acc.w *= inv;
        reinterpret_cast<float4*>(out + (size_t)token * OUT_W + E_DIM)[lane] = acc;
    }

    // ---- drain bulk load, then bulk store SMEM -> out row (TMA path) ----
    if (lane == 0) {
        uint32_t done = 0;
        while (!done) {
            asm volatile(
                "{ .reg .pred p;\n\t"
                "  mbarrier.try_wait.parity.shared::cta.b64 p, [%1], 0, 0x989680;\n\t"
                "  selp.b32 %0, 1, 0, p; }"
                : "=r"(done) : "r"(mbar_addr) : "memory");
        }
        asm volatile("cp.async.bulk.global.shared::cta.bulk_group [%0], [%1], %2;"
                     :: "l"(out + (size_t)token * OUT_W),
                        "r"(buf_addr), "r"(4096u) : "memory");
        asm volatile("cp.async.bulk.commit_group;" ::: "memory");
        asm volatile("cp.async.bulk.wait_group 0;" ::: "memory");
    }
}

extern "C" void kernel_launch(void* const* d_in, const int* in_sizes, int n_in,
                              void* d_out, int out_size)
{
    const int*   inputs  = (const int*)  d_in[0];
    const int*   triples = (const int*)  d_in[1];
    const int*   flags   = (const int*)  d_in[2];
    const float* emb     = (const float*)d_in[3];
    const float* ent     = (const float*)d_in[4];
    float*       out     = (float*)      d_out;

    fuse_triples_tma_kernel<<<NTOK / WPB, 32 * WPB>>>(inputs, triples, flags,
                                                      emb, ent, out);
}